// round 16
// baseline (speedup 1.0000x reference)
#include <cuda_runtime.h>
#include <cuda_fp16.h>
#include <math.h>

#define NN    50000
#define EE    200000
#define ET    250000   // EE + NN self loops
#define GG    2000
#define DMF   512
#define NHEAD 4
#define HIDD  128
#define NEG_SLOPE 0.2f
#define BN_EPS 1e-5f

// ---------------- scratch (device globals; no allocation allowed) ----------
__device__ __half d_h   [NN * DMF];    // h = x @ W (fp16, gather source)
__device__ __half d_xh  [NN * 64];     // x converted to fp16 (layer-0 A)
__device__ __half d_xbh [NN * DMF];    // layer output in fp16 (A for layers 1,2)
__device__ __half d_wt0 [DMF * 64];    // W0^T fp16 [n][k]
__device__ __half d_wt1 [DMF * DMF];   // W1^T fp16 [n][k]
__device__ __half d_wt2 [DMF * DMF];   // W2^T fp16 [n][k]
__device__ float  d_agg [NN * DMF];    // aggregated output (bias folded)
__device__ float  d_ssrc[NN * NHEAD];
__device__ float  d_sdst[NN * NHEAD];
__device__ float  d_bnsum[DMF];
__device__ float  d_bnss [DMF];
__device__ float  d_scale[DMF];
__device__ float  d_shift[DMF];
__device__ int    d_bn_done;           // last-block counter (self-resetting)
__device__ float  d_gsum [GG * DMF];
__device__ int    d_gmaxi[GG * DMF];
__device__ float  d_gcnt [GG];
__device__ float  d_h1   [GG * 128];
// CSR (rebuilt each launch; edge structure constant across the 3 layers)
__device__ int    d_deg   [NN];
__device__ int    d_rowptr[NN];
__device__ int    d_cursor[NN];
__device__ int    d_eid   [ET];

// ---------------- helpers ----------------
__device__ __forceinline__ void redAddV4(float* p, float4 v) {
    asm volatile("red.global.add.v4.f32 [%0], {%1,%2,%3,%4};"
                 :: "l"(p), "f"(v.x), "f"(v.y), "f"(v.z), "f"(v.w) : "memory");
}

__device__ __forceinline__ void cpAsync16(void* smem_dst, const void* gsrc, int src_sz) {
    unsigned d = (unsigned)__cvta_generic_to_shared(smem_dst);
    asm volatile("cp.async.cg.shared.global [%0], [%1], 16, %2;"
                 :: "r"(d), "l"(gsrc), "r"(src_sz));
}

__device__ __forceinline__ float leakyf(float v) {
    return (v > 0.f) ? v : NEG_SLOPE * v;
}

// ---------------- init: deg zero + bn zero + x conversion (merged) --------
__global__ void init_convert_kernel(const float* __restrict__ x) {
    int i = blockIdx.x * blockDim.x + threadIdx.x;
    if (i < NN * 64 / 2) {
        float2 v = *(const float2*)(x + 2 * i);
        *((__half2*)d_xh + i) = __floats2half2_rn(v.x, v.y);
    }
    if (i < NN) d_deg[i] = 0;
    if (i < DMF) { d_bnsum[i] = 0.f; d_bnss[i] = 0.f; }
    if (i == 0) d_bn_done = 0;
}

// All three W[k][n] fp32 -> Wt[n][k] fp16 transposes in one launch (z = layer)
__global__ void __launch_bounds__(256)
transpose_all_kernel(const float* __restrict__ W0,
                     const float* __restrict__ W1,
                     const float* __restrict__ W2) {
    __shared__ float tile[32][33];
    int l = blockIdx.z;
    const float* W = (l == 0) ? W0 : (l == 1) ? W1 : W2;
    __half* Wt = (l == 0) ? d_wt0 : (l == 1) ? d_wt1 : d_wt2;
    int K = (l == 0) ? 64 : DMF;
    int k0 = blockIdx.y * 32;
    if (k0 >= K) return;
    int n0 = blockIdx.x * 32;
    int tx = threadIdx.x & 31, ty0 = threadIdx.x >> 5;   // 32 x 8
#pragma unroll
    for (int q = 0; q < 4; q++) {
        int ty = ty0 + q * 8;
        tile[ty][tx] = W[(long long)(k0 + ty) * DMF + n0 + tx];
    }
    __syncthreads();
#pragma unroll
    for (int q = 0; q < 4; q++) {
        int ty = ty0 + q * 8;
        Wt[(long long)(n0 + ty) * K + k0 + tx] = __float2half(tile[tx][ty]);
    }
}

// ---------------- fp16 tensor-core GEMM + fused score epilogue ------------
// EXACT round-10/12 verified 2-stage pipeline (the 3-stage single-sync
// variant regressed +360us in round 13 — do not reintroduce).
// C[M,512] = A[M,K] @ Wt^T, A fp16 [m][k], Wt fp16 [n][k]. 128x128 tile,
// BK=32, 256 threads (8 warps 2x4), warp tile 64x32, m16n8k16 fp16 MMA,
// fp32 accum. A and B fragments via ldmatrix.x4; pitch 40 halves (80B)
// conflict-free. No min-blocks cap (round-11: spills cost more than occ).
#define HPITCH 40
#define WPITCH 20

__global__ void __launch_bounds__(256)
gemm_f16_kernel(const __half* __restrict__ A, const __half* __restrict__ Bt,
                __half* __restrict__ C, int M, int K,
                const float* __restrict__ a_s, const float* __restrict__ a_d) {
    __shared__ __half Ah[2][128 * HPITCH];
    __shared__ __half Bh[2][128 * HPITCH];
    __shared__ float s_ps[4][128];
    __shared__ float s_pd[4][128];

    const int bx = blockIdx.x;   // N tile == head (0..3)
    const int by = blockIdx.y;   // M tile
    const int tid = threadIdx.x;
    const int warp = tid >> 5, lane = tid & 31;
    const int wr = warp & 1, wc = warp >> 1;      // 2 x 4 warp grid
    const int m0 = wr * 64, n0 = wc * 32;
    const int r = lane >> 2, c = lane & 3;

    // ldmatrix lane addressing: group g (0..3), row-in-group lr (0..7)
    const int g = lane >> 3, lr = lane & 7;
    const unsigned aAh0 = (unsigned)__cvta_generic_to_shared(&Ah[0][0]);
    const unsigned aBh0 = (unsigned)__cvta_generic_to_shared(&Bh[0][0]);
    const unsigned laneBaseA =
        (unsigned)((m0 + (g & 1) * 8 + lr) * (HPITCH * 2) + (g >> 1) * 16);
    // B x4: matrix m -> (j = m>>1, k-half = m&1); row = lr
    const unsigned laneBaseB =
        (unsigned)(((n0 + (g >> 1) * 8 + lr) * WPITCH + (g & 1) * 4) * 4);

    float acc[4][4][4];
#pragma unroll
    for (int i = 0; i < 4; i++)
#pragma unroll
        for (int j = 0; j < 4; j++)
#pragma unroll
            for (int q = 0; q < 4; q++) acc[i][j][q] = 0.0f;

    const int KT = K >> 5;

    auto load_tile = [&](int st, int k0) {
#pragma unroll
        for (int p = 0; p < 2; p++) {
            int f = tid + p * 256;               // 0..511
            int row = f >> 2, ch = f & 3;        // 128 rows x 4 chunks(8 halves)
            int gm = by * 128 + row;
            cpAsync16(&Ah[st][row * HPITCH + ch * 8],
                      A + (long long)gm * K + k0 + ch * 8,
                      (gm < M) ? 16 : 0);
        }
#pragma unroll
        for (int p = 0; p < 2; p++) {
            int f = tid + p * 256;
            int row = f >> 2, ch = f & 3;
            cpAsync16(&Bh[st][row * HPITCH + ch * 8],
                      Bt + (long long)(bx * 128 + row) * K + k0 + ch * 8,
                      16);
        }
    };

    load_tile(0, 0);
    asm volatile("cp.async.commit_group;");

    for (int kt = 0; kt < KT; kt++) {
        const int st = kt & 1;
        if (kt + 1 < KT) load_tile(st ^ 1, (kt + 1) * 32);
        asm volatile("cp.async.commit_group;");
        asm volatile("cp.async.wait_group 1;");
        __syncthreads();

        const unsigned aSt = aAh0 + (unsigned)(st * 128 * HPITCH * 2) + laneBaseA;
        const unsigned bSt = aBh0 + (unsigned)(st * 128 * HPITCH * 2) + laneBaseB;
#pragma unroll
        for (int ks = 0; ks < 2; ks++) {
            unsigned bf[4][2];
#pragma unroll
            for (int jj = 0; jj < 2; jj++) {
                unsigned addr = bSt + (unsigned)(ks * 32 + jj * 16 * WPITCH * 4);
                asm volatile(
                    "ldmatrix.sync.aligned.m8n8.x4.shared.b16 {%0,%1,%2,%3}, [%4];"
                    : "=r"(bf[jj*2][0]), "=r"(bf[jj*2][1]),
                      "=r"(bf[jj*2+1][0]), "=r"(bf[jj*2+1][1])
                    : "r"(addr));
            }
#pragma unroll
            for (int i = 0; i < 4; i++) {
                unsigned addr = aSt + (unsigned)(i * 16 * HPITCH * 2 + ks * 32);
                unsigned a0, a1, a2, a3;
                asm volatile(
                    "ldmatrix.sync.aligned.m8n8.x4.shared.b16 {%0,%1,%2,%3}, [%4];"
                    : "=r"(a0), "=r"(a1), "=r"(a2), "=r"(a3) : "r"(addr));
#pragma unroll
                for (int j = 0; j < 4; j++) {
                    asm volatile(
                        "mma.sync.aligned.m16n8k16.row.col.f32.f16.f16.f32 "
                        "{%0,%1,%2,%3},{%4,%5,%6,%7},{%8,%9},{%0,%1,%2,%3};\n"
                        : "+f"(acc[i][j][0]), "+f"(acc[i][j][1]),
                          "+f"(acc[i][j][2]), "+f"(acc[i][j][3])
                        : "r"(a0), "r"(a1), "r"(a2), "r"(a3),
                          "r"(bf[j][0]), "r"(bf[j][1]));
                }
            }
        }
        __syncthreads();
    }

    // ---- store C tile as fp16 ----
#pragma unroll
    for (int i = 0; i < 4; i++) {
        int row0 = by * 128 + m0 + i * 16 + r;
#pragma unroll
        for (int j = 0; j < 4; j++) {
            int col = bx * 128 + n0 + j * 8 + 2 * c;
            if (row0 < M)
                *(__half2*)(C + (long long)row0 * DMF + col) =
                    __floats2half2_rn(acc[i][j][0], acc[i][j][1]);
            if (row0 + 8 < M)
                *(__half2*)(C + (long long)(row0 + 8) * DMF + col) =
                    __floats2half2_rn(acc[i][j][2], acc[i][j][3]);
        }
    }

    // ---- fused attention-score epilogue (head == bx); smem reduce ----
    float asr[4][2], adr[4][2];
#pragma unroll
    for (int j = 0; j < 4; j++) {
#pragma unroll
        for (int p = 0; p < 2; p++) {
            int colL = n0 + j * 8 + 2 * c + p;
            asr[j][p] = a_s[bx * HIDD + colL];
            adr[j][p] = a_d[bx * HIDD + colL];
        }
    }
#pragma unroll
    for (int i = 0; i < 4; i++) {
        float ps_lo = 0.f, ps_hi = 0.f, pd_lo = 0.f, pd_hi = 0.f;
#pragma unroll
        for (int j = 0; j < 4; j++) {
            ps_lo = fmaf(acc[i][j][0], asr[j][0], fmaf(acc[i][j][1], asr[j][1], ps_lo));
            ps_hi = fmaf(acc[i][j][2], asr[j][0], fmaf(acc[i][j][3], asr[j][1], ps_hi));
            pd_lo = fmaf(acc[i][j][0], adr[j][0], fmaf(acc[i][j][1], adr[j][1], pd_lo));
            pd_hi = fmaf(acc[i][j][2], adr[j][0], fmaf(acc[i][j][3], adr[j][1], pd_hi));
        }
#pragma unroll
        for (int off = 1; off < 4; off <<= 1) {
            ps_lo += __shfl_xor_sync(0xffffffffu, ps_lo, off);
            ps_hi += __shfl_xor_sync(0xffffffffu, ps_hi, off);
            pd_lo += __shfl_xor_sync(0xffffffffu, pd_lo, off);
            pd_hi += __shfl_xor_sync(0xffffffffu, pd_hi, off);
        }
        if (c == 0) {
            int rl = m0 + i * 16 + r;
            s_ps[wc][rl]     = ps_lo;  s_pd[wc][rl]     = pd_lo;
            s_ps[wc][rl + 8] = ps_hi;  s_pd[wc][rl + 8] = pd_hi;
        }
    }
    __syncthreads();
    if (tid < 128) {
        int row = by * 128 + tid;
        if (row < M) {
            d_ssrc[row * NHEAD + bx] =
                s_ps[0][tid] + s_ps[1][tid] + s_ps[2][tid] + s_ps[3][tid];
            d_sdst[row * NHEAD + bx] =
                s_pd[0][tid] + s_pd[1][tid] + s_pd[2][tid] + s_pd[3][tid];
        }
    }
}

// ---------------- CSR build (once per launch) ----------------
__global__ void count_deg_kernel(const int* __restrict__ ei) {
    int e = blockIdx.x * blockDim.x + threadIdx.x;
    if (e >= ET) return;
    int dst = (e < EE) ? ei[EE + e] : e - EE;
    atomicAdd(&d_deg[dst], 1);
}

__global__ void __launch_bounds__(1024)
scan_kernel() {
    __shared__ int partial[1024];
    const int C = (NN + 1023) / 1024;       // 49
    int t = threadIdx.x;
    int lo = t * C, hi = min(lo + C, NN);
    int s = 0;
    for (int i = lo; i < hi; i++) s += d_deg[i];
    partial[t] = s;
    __syncthreads();
    for (int off = 1; off < 1024; off <<= 1) {
        int v = partial[t];
        int add = (t >= off) ? partial[t - off] : 0;
        __syncthreads();
        partial[t] = v + add;
        __syncthreads();
    }
    int run = (t == 0) ? 0 : partial[t - 1];
    for (int i = lo; i < hi; i++) {
        d_rowptr[i] = run;
        d_cursor[i] = run;
        run += d_deg[i];
    }
}

__global__ void scatter_kernel(const int* __restrict__ ei) {
    int e = blockIdx.x * blockDim.x + threadIdx.x;
    if (e >= ET) return;
    int dst = (e < EE) ? ei[EE + e] : e - EE;
    int pos = atomicAdd(&d_cursor[dst], 1);
    d_eid[pos] = e;
}

// ---------------- warp-per-node fused softmax + fp16 gather ---------------
__global__ void __launch_bounds__(256)
aggregate_warp_kernel(const int* __restrict__ ei,
                      const float* __restrict__ bias) {
    const int lane = threadIdx.x & 31;
    const int n = blockIdx.x * 8 + (threadIdx.x >> 5);
    if (n >= NN) return;

    const int start = d_rowptr[n];
    const int deg   = d_deg[n];
    const int head  = lane >> 3;          // lane's 16 cols = [lane*16, +16)

    float4 sd = *(const float4*)(d_sdst + n * NHEAD);

    // ---- phase 1: per-head segment max (warp-parallel over edges) ----
    float4 m4 = make_float4(-1e30f, -1e30f, -1e30f, -1e30f);
    for (int b = lane; b < deg; b += 32) {
        int e = d_eid[start + b];
        int s = (e < EE) ? ei[e] : e - EE;
        float4 ss = *(const float4*)(d_ssrc + s * NHEAD);
        m4.x = fmaxf(m4.x, leakyf(ss.x + sd.x));
        m4.y = fmaxf(m4.y, leakyf(ss.y + sd.y));
        m4.z = fmaxf(m4.z, leakyf(ss.z + sd.z));
        m4.w = fmaxf(m4.w, leakyf(ss.w + sd.w));
    }
#pragma unroll
    for (int off = 16; off; off >>= 1) {
        m4.x = fmaxf(m4.x, __shfl_xor_sync(0xffffffffu, m4.x, off));
        m4.y = fmaxf(m4.y, __shfl_xor_sync(0xffffffffu, m4.y, off));
        m4.z = fmaxf(m4.z, __shfl_xor_sync(0xffffffffu, m4.z, off));
        m4.w = fmaxf(m4.w, __shfl_xor_sync(0xffffffffu, m4.w, off));
    }

    // ---- phase 2: exp weights + denominator + fp16 weighted gather ----
    float4 acc0 = make_float4(0.f, 0.f, 0.f, 0.f);
    float4 acc1 = acc0, acc2 = acc0, acc3 = acc0;
    float4 lden = acc0;

    for (int base = 0; base < deg; base += 32) {
        int cnt = min(32, deg - base);
        int s = 0;
        float4 w4 = make_float4(0.f, 0.f, 0.f, 0.f);
        if (lane < cnt) {
            int e = d_eid[start + base + lane];
            s = (e < EE) ? ei[e] : e - EE;
            float4 ss = *(const float4*)(d_ssrc + s * NHEAD);
            w4.x = expf(leakyf(ss.x + sd.x) - m4.x);
            w4.y = expf(leakyf(ss.y + sd.y) - m4.y);
            w4.z = expf(leakyf(ss.z + sd.z) - m4.z);
            w4.w = expf(leakyf(ss.w + sd.w) - m4.w);
            lden.x += w4.x; lden.y += w4.y; lden.z += w4.z; lden.w += w4.w;
        }
        for (int i = 0; i < cnt; i++) {
            int   si = __shfl_sync(0xffffffffu, s, i);
            float wx = __shfl_sync(0xffffffffu, w4.x, i);
            float wy = __shfl_sync(0xffffffffu, w4.y, i);
            float wz = __shfl_sync(0xffffffffu, w4.z, i);
            float ww = __shfl_sync(0xffffffffu, w4.w, i);
            float wgt = (head == 0) ? wx : (head == 1) ? wy : (head == 2) ? wz : ww;
            const uint4* hp = (const uint4*)(d_h + (long long)si * DMF) + lane * 2;
            uint4 u0 = hp[0], u1 = hp[1];
            const __half2* p0 = (const __half2*)&u0;
            const __half2* p1 = (const __half2*)&u1;
            float2 f;
            f = __half22float2(p0[0]);
            acc0.x = fmaf(wgt, f.x, acc0.x); acc0.y = fmaf(wgt, f.y, acc0.y);
            f = __half22float2(p0[1]);
            acc0.z = fmaf(wgt, f.x, acc0.z); acc0.w = fmaf(wgt, f.y, acc0.w);
            f = __half22float2(p0[2]);
            acc1.x = fmaf(wgt, f.x, acc1.x); acc1.y = fmaf(wgt, f.y, acc1.y);
            f = __half22float2(p0[3]);
            acc1.z = fmaf(wgt, f.x, acc1.z); acc1.w = fmaf(wgt, f.y, acc1.w);
            f = __half22float2(p1[0]);
            acc2.x = fmaf(wgt, f.x, acc2.x); acc2.y = fmaf(wgt, f.y, acc2.y);
            f = __half22float2(p1[1]);
            acc2.z = fmaf(wgt, f.x, acc2.z); acc2.w = fmaf(wgt, f.y, acc2.w);
            f = __half22float2(p1[2]);
            acc3.x = fmaf(wgt, f.x, acc3.x); acc3.y = fmaf(wgt, f.y, acc3.y);
            f = __half22float2(p1[3]);
            acc3.z = fmaf(wgt, f.x, acc3.z); acc3.w = fmaf(wgt, f.y, acc3.w);
        }
    }

#pragma unroll
    for (int off = 16; off; off >>= 1) {
        lden.x += __shfl_xor_sync(0xffffffffu, lden.x, off);
        lden.y += __shfl_xor_sync(0xffffffffu, lden.y, off);
        lden.z += __shfl_xor_sync(0xffffffffu, lden.z, off);
        lden.w += __shfl_xor_sync(0xffffffffu, lden.w, off);
    }
    float den = (head == 0) ? lden.x : (head == 1) ? lden.y
              : (head == 2) ? lden.z : lden.w;
    float rd = 1.0f / den;

    const float4* bp = (const float4*)bias + lane * 4;
    float4* op = (float4*)(d_agg + (long long)n * DMF) + lane * 4;
    float4 b0 = bp[0], b1 = bp[1], b2 = bp[2], b3 = bp[3];
    float4 o;
    o.x = fmaf(acc0.x, rd, b0.x); o.y = fmaf(acc0.y, rd, b0.y);
    o.z = fmaf(acc0.z, rd, b0.z); o.w = fmaf(acc0.w, rd, b0.w); op[0] = o;
    o.x = fmaf(acc1.x, rd, b1.x); o.y = fmaf(acc1.y, rd, b1.y);
    o.z = fmaf(acc1.z, rd, b1.z); o.w = fmaf(acc1.w, rd, b1.w); op[1] = o;
    o.x = fmaf(acc2.x, rd, b2.x); o.y = fmaf(acc2.y, rd, b2.y);
    o.z = fmaf(acc2.z, rd, b2.z); o.w = fmaf(acc2.w, rd, b2.w); op[2] = o;
    o.x = fmaf(acc3.x, rd, b3.x); o.y = fmaf(acc3.y, rd, b3.y);
    o.z = fmaf(acc3.z, rd, b3.z); o.w = fmaf(acc3.w, rd, b3.w); op[3] = o;
}

// ---------------- batch norm: stats with fused last-block finalize --------
__global__ void __launch_bounds__(512)
bn_stats_kernel(const float* __restrict__ g, const float* __restrict__ be,
                int nblocks) {
    __shared__ int is_last;
    int c = threadIdx.x;
    int r0 = blockIdx.x * 64;
    int rend = min(r0 + 64, NN);
    float s = 0.f, ss = 0.f;
    for (int r = r0; r < rend; r++) {
        float v = d_agg[(long long)r * DMF + c];
        s += v; ss += v * v;
    }
    atomicAdd(&d_bnsum[c], s);
    atomicAdd(&d_bnss[c], ss);

    __threadfence();
    if (c == 0) {
        int old = atomicAdd(&d_bn_done, 1);
        is_last = (old == nblocks - 1) ? 1 : 0;
    }
    __syncthreads();
    if (is_last) {
        float mean = d_bnsum[c] * (1.0f / NN);
        float var  = d_bnss[c] * (1.0f / NN) - mean * mean;
        float sc = g[c] * rsqrtf(var + BN_EPS);
        d_scale[c] = sc;
        d_shift[c] = be[c] - mean * sc;
        d_bnsum[c] = 0.f;
        d_bnss[c]  = 0.f;
        if (c == 0) d_bn_done = 0;
    }
}

// BN + ReLU -> next-layer A in fp16
__global__ void bn_apply_kernel() {
    int i = blockIdx.x * blockDim.x + threadIdx.x;
    if (i >= NN * DMF / 2) return;
    int c = (2 * i) & (DMF - 1);
    float2 a = *(const float2*)(d_agg + 2 * i);
    float vx = fmaxf(fmaf(a.x, d_scale[c],     d_shift[c]),     0.f);
    float vy = fmaxf(fmaf(a.y, d_scale[c + 1], d_shift[c + 1]), 0.f);
    *((__half2*)d_xbh + i) = __floats2half2_rn(vx, vy);
}

// last layer: BN + ReLU + mean/max pooling fused
__global__ void bn_apply_pool_kernel(const int* __restrict__ batch) {
    int i = blockIdx.x * blockDim.x + threadIdx.x;
    if (i >= NN * 128) return;              // float4 lanes
    int n = i >> 7, c4 = i & 127;
    int c = c4 * 4;
    float4 a = *(const float4*)(d_agg + (long long)n * DMF + c);
    float4 v;
    v.x = fmaxf(fmaf(a.x, d_scale[c + 0], d_shift[c + 0]), 0.f);
    v.y = fmaxf(fmaf(a.y, d_scale[c + 1], d_shift[c + 1]), 0.f);
    v.z = fmaxf(fmaf(a.z, d_scale[c + 2], d_shift[c + 2]), 0.f);
    v.w = fmaxf(fmaf(a.w, d_scale[c + 3], d_shift[c + 3]), 0.f);
    int g = batch[n];
    redAddV4(d_gsum + (long long)g * DMF + c, v);
    int* mp = d_gmaxi + (long long)g * DMF + c;
    atomicMax(mp + 0, __float_as_int(v.x));   // values >= 0 after ReLU
    atomicMax(mp + 1, __float_as_int(v.y));
    atomicMax(mp + 2, __float_as_int(v.z));
    atomicMax(mp + 3, __float_as_int(v.w));
}

// ---------------- pooling init ----------------
__global__ void pool_init_kernel() {
    int i = blockIdx.x * blockDim.x + threadIdx.x;
    if (i < GG * DMF) { d_gsum[i] = 0.f; d_gmaxi[i] = 0; }
    if (i < GG) d_gcnt[i] = 0.f;
}

__global__ void pool_cnt_kernel(const int* __restrict__ batch) {
    int n = blockIdx.x * blockDim.x + threadIdx.x;
    if (n < NN) atomicAdd(&d_gcnt[batch[n]], 1.0f);
}

// ---------------- graph-level MLP ----------------
__global__ void __launch_bounds__(128)
mlp1_kernel(const float* __restrict__ c1w, const float* __restrict__ c1b) {
    __shared__ float hrow[8][1024];
    int g0 = blockIdx.x * 8, t = threadIdx.x;
#pragma unroll
    for (int gi = 0; gi < 8; gi++) {
        int g = g0 + gi;
        float inv = 1.0f / fmaxf(d_gcnt[g], 1.0f);
        for (int c = t; c < DMF; c += 128) {
            hrow[gi][c]       = d_gsum[g * DMF + c] * inv;
            hrow[gi][DMF + c] = __int_as_float(d_gmaxi[g * DMF + c]);
        }
    }
    __syncthreads();
    float acc[8];
    float b = c1b[t];
#pragma unroll
    for (int gi = 0; gi < 8; gi++) acc[gi] = b;
    for (int k = 0; k < 1024; k++) {
        float wv = c1w[k * 128 + t];
#pragma unroll
        for (int gi = 0; gi < 8; gi++)
            acc[gi] = fmaf(hrow[gi][k], wv, acc[gi]);
    }
#pragma unroll
    for (int gi = 0; gi < 8; gi++)
        d_h1[(g0 + gi) * 128 + t] = fmaxf(acc[gi], 0.f);
}

// mlp2 + mlp3 merged: per-graph block of 64 threads
__global__ void __launch_bounds__(64)
mlp23_kernel(const float* __restrict__ c2w, const float* __restrict__ c2b,
             const float* __restrict__ c3w, const float* __restrict__ c3b,
             float* __restrict__ out) {
    __shared__ float hrow[128];
    __shared__ float h2s[64];
    int g = blockIdx.x, t = threadIdx.x;
    hrow[t]      = d_h1[g * 128 + t];
    hrow[64 + t] = d_h1[g * 128 + 64 + t];
    __syncthreads();
    float acc = c2b[t];
    for (int k = 0; k < 128; k++) acc = fmaf(hrow[k], c2w[k * 64 + t], acc);
    h2s[t] = fmaxf(acc, 0.f);
    __syncthreads();
    if (t < 32) {
        float v = h2s[t] * c3w[t] + h2s[t + 32] * c3w[t + 32];
#pragma unroll
        for (int off = 16; off; off >>= 1)
            v += __shfl_down_sync(0xffffffffu, v, off);
        if (t == 0)
            out[g] = 1.0f / (1.0f + expf(-(v + c3b[0])));
    }
}

// ---------------- launch ----------------
extern "C" void kernel_launch(void* const* d_in, const int* in_sizes, int n_in,
                              void* d_out, int out_size) {
    const float* x     = (const float*)d_in[0];
    const int*   ei    = (const int*)  d_in[1];
    const int*   batch = (const int*)  d_in[2];

    const float* W [3] = {(const float*)d_in[3],  (const float*)d_in[9],  (const float*)d_in[15]};
    const float* AS[3] = {(const float*)d_in[4],  (const float*)d_in[10], (const float*)d_in[16]};
    const float* AD[3] = {(const float*)d_in[5],  (const float*)d_in[11], (const float*)d_in[17]};
    const float* BB[3] = {(const float*)d_in[6],  (const float*)d_in[12], (const float*)d_in[18]};
    const float* GM[3] = {(const float*)d_in[7],  (const float*)d_in[13], (const float*)d_in[19]};
    const float* BE[3] = {(const float*)d_in[8],  (const float*)d_in[14], (const float*)d_in[20]};

    const float* c1w = (const float*)d_in[21];
    const float* c1b = (const float*)d_in[22];
    const float* c2w = (const float*)d_in[23];
    const float* c2b = (const float*)d_in[24];
    const float* c3w = (const float*)d_in[25];
    const float* c3b = (const float*)d_in[26];
    float* out = (float*)d_out;

    __half* hbuf;  cudaGetSymbolAddress((void**)&hbuf,  d_h);
    __half* xhb;   cudaGetSymbolAddress((void**)&xhb,   d_xh);
    __half* xbhb;  cudaGetSymbolAddress((void**)&xbhb,  d_xbh);
    __half* wt0;   cudaGetSymbolAddress((void**)&wt0,   d_wt0);
    __half* wt1;   cudaGetSymbolAddress((void**)&wt1,   d_wt1);
    __half* wt2;   cudaGetSymbolAddress((void**)&wt2,   d_wt2);
    __half* WT[3] = {wt0, wt1, wt2};

    const int KDIM[3] = {64, DMF, DMF};
    const int THR = 256;

    // ---- init + x conversion (merged) + all transposes (one launch) ----
    int icn = NN * 64 / 2;
    init_convert_kernel<<<(icn + THR - 1) / THR, THR>>>(x);

    dim3 tg(DMF / 32, DMF / 32, 3);
    transpose_all_kernel<<<tg, 256>>>(W[0], W[1], W[2]);

    dim3 ggrid(DMF / 128, (NN + 127) / 128);
    gemm_f16_kernel<<<ggrid, 256>>>(xhb, wt0, hbuf, NN, KDIM[0], AS[0], AD[0]);

    // ---- CSR build + pooling init (independent of GEMM) ----
    count_deg_kernel<<<(ET + THR - 1) / THR, THR>>>(ei);
    scan_kernel<<<1, 1024>>>();
    scatter_kernel<<<(ET + THR - 1) / THR, THR>>>(ei);

    int pil = GG * DMF;
    pool_init_kernel<<<(pil + THR - 1) / THR, THR>>>();
    pool_cnt_kernel<<<(NN + THR - 1) / THR, THR>>>(batch);

    const int bnblocks = (NN + 63) / 64;

    for (int l = 0; l < 3; l++) {
        if (l > 0)
            gemm_f16_kernel<<<ggrid, 256>>>(xbhb, WT[l], hbuf, NN, KDIM[l], AS[l], AD[l]);

        aggregate_warp_kernel<<<(NN + 7) / 8, 256>>>(ei, BB[l]);

        bn_stats_kernel<<<bnblocks, DMF>>>(GM[l], BE[l], bnblocks);

        if (l < 2) {
            int nel = NN * DMF / 2;
            bn_apply_kernel<<<(nel + THR - 1) / THR, THR>>>();
        } else {
            int pft = NN * 128;
            bn_apply_pool_kernel<<<(pft + THR - 1) / THR, THR>>>(batch);
        }
    }

    mlp1_kernel<<<GG / 8, 128>>>(c1w, c1b);
    mlp23_kernel<<<GG, 64>>>(c2w, c2b, c3w, c3b, out);
}

// round 17
// speedup vs baseline: 1.4273x; 1.4273x over previous
#include <cuda_runtime.h>
#include <cuda_fp16.h>
#include <math.h>

#define NN    50000
#define EE    200000
#define ET    250000   // EE + NN self loops
#define GG    2000
#define DMF   512
#define NHEAD 4
#define HIDD  128
#define NEG_SLOPE 0.2f
#define BN_EPS 1e-5f

// ---------------- scratch (device globals; no allocation allowed) ----------
__device__ __half d_h   [NN * DMF];    // h = x @ W (fp16, gather source)
__device__ __half d_xh  [NN * 64];     // x converted to fp16 (layer-0 A)
__device__ __half d_xbh [NN * DMF];    // layer output in fp16 (A for layers 1,2)
__device__ __half d_wt0 [DMF * 64];    // W0^T fp16 [n][k]
__device__ __half d_wt1 [DMF * DMF];   // W1^T fp16 [n][k]
__device__ __half d_wt2 [DMF * DMF];   // W2^T fp16 [n][k]
__device__ float  d_agg [NN * DMF];    // aggregated output (bias folded)
__device__ float  d_ssrc[NN * NHEAD];
__device__ float  d_sdst[NN * NHEAD];
__device__ float  d_bnsum[DMF];
__device__ float  d_bnss [DMF];
__device__ float  d_scale[DMF];
__device__ float  d_shift[DMF];
__device__ float  d_gsum [GG * DMF];
__device__ int    d_gmaxi[GG * DMF];
__device__ float  d_gcnt [GG];
__device__ float  d_h1   [GG * 128];
__device__ float  d_h2   [GG * 64];
// CSR (rebuilt each launch; edge structure constant across the 3 layers)
__device__ int    d_deg   [NN];
__device__ int    d_rowptr[NN];
__device__ int    d_cursor[NN];
__device__ int    d_eid   [ET];

// ---------------- helpers ----------------
__device__ __forceinline__ void redAddV4(float* p, float4 v) {
    asm volatile("red.global.add.v4.f32 [%0], {%1,%2,%3,%4};"
                 :: "l"(p), "f"(v.x), "f"(v.y), "f"(v.z), "f"(v.w) : "memory");
}

__device__ __forceinline__ void cpAsync16(void* smem_dst, const void* gsrc, int src_sz) {
    unsigned d = (unsigned)__cvta_generic_to_shared(smem_dst);
    asm volatile("cp.async.cg.shared.global [%0], [%1], 16, %2;"
                 :: "r"(d), "l"(gsrc), "r"(src_sz));
}

__device__ __forceinline__ float leakyf(float v) {
    return (v > 0.f) ? v : NEG_SLOPE * v;
}

// ---------------- init: degree zero + bn accumulator zero -----------------
__global__ void init_zero_kernel() {
    int n = blockIdx.x * blockDim.x + threadIdx.x;
    if (n < NN) d_deg[n] = 0;
    if (n < DMF) { d_bnsum[n] = 0.f; d_bnss[n] = 0.f; }
}

// ---------------- input conversion ----------------
__global__ void convert_x_kernel(const float* __restrict__ x) {
    int i = blockIdx.x * blockDim.x + threadIdx.x;
    if (i >= NN * 64 / 2) return;
    float2 v = *(const float2*)(x + 2 * i);
    *((__half2*)d_xh + i) = __floats2half2_rn(v.x, v.y);
}

// W[k][n] fp32 -> Wt[n][k] fp16, 32x32 smem tile transpose
__global__ void __launch_bounds__(256)
transpose_w_kernel(const float* __restrict__ W, __half* __restrict__ Wt, int K) {
    __shared__ float tile[32][33];
    int n0 = blockIdx.x * 32, k0 = blockIdx.y * 32;
    int tx = threadIdx.x & 31, ty0 = threadIdx.x >> 5;   // 32 x 8
#pragma unroll
    for (int q = 0; q < 4; q++) {
        int ty = ty0 + q * 8;
        tile[ty][tx] = W[(long long)(k0 + ty) * DMF + n0 + tx];
    }
    __syncthreads();
#pragma unroll
    for (int q = 0; q < 4; q++) {
        int ty = ty0 + q * 8;
        Wt[(long long)(n0 + ty) * K + k0 + tx] = __float2half(tile[tx][ty]);
    }
}

// ---------------- fp16 tensor-core GEMM + fused score epilogue ------------
// C[M,512] = A[M,K] @ Wt^T, A fp16 [m][k], Wt fp16 [n][k]. 128x128 tile,
// BK=32, 256 threads (8 warps 2x4), warp tile 64x32, m16n8k16 fp16 MMA,
// fp32 accum. A and B fragments via ldmatrix.x4; pitch 40 halves (80B)
// conflict-free. NO min-blocks cap: this kernel wants registers (round-11
// regression showed spills cost more than the occupancy gain).
#define HPITCH 40
#define WPITCH 20

__global__ void __launch_bounds__(256)
gemm_f16_kernel(const __half* __restrict__ A, const __half* __restrict__ Bt,
                __half* __restrict__ C, int M, int K,
                const float* __restrict__ a_s, const float* __restrict__ a_d) {
    __shared__ __half Ah[2][128 * HPITCH];
    __shared__ __half Bh[2][128 * HPITCH];
    __shared__ float s_ps[4][128];
    __shared__ float s_pd[4][128];

    const int bx = blockIdx.x;   // N tile == head (0..3)
    const int by = blockIdx.y;   // M tile
    const int tid = threadIdx.x;
    const int warp = tid >> 5, lane = tid & 31;
    const int wr = warp & 1, wc = warp >> 1;      // 2 x 4 warp grid
    const int m0 = wr * 64, n0 = wc * 32;
    const int r = lane >> 2, c = lane & 3;

    // ldmatrix lane addressing: group g (0..3), row-in-group lr (0..7)
    const int g = lane >> 3, lr = lane & 7;
    const unsigned aAh0 = (unsigned)__cvta_generic_to_shared(&Ah[0][0]);
    const unsigned aBh0 = (unsigned)__cvta_generic_to_shared(&Bh[0][0]);
    const unsigned laneBaseA =
        (unsigned)((m0 + (g & 1) * 8 + lr) * (HPITCH * 2) + (g >> 1) * 16);
    // B x4: matrix m -> (j = m>>1, k-half = m&1); row = lr
    const unsigned laneBaseB =
        (unsigned)(((n0 + (g >> 1) * 8 + lr) * WPITCH + (g & 1) * 4) * 4);

    float acc[4][4][4];
#pragma unroll
    for (int i = 0; i < 4; i++)
#pragma unroll
        for (int j = 0; j < 4; j++)
#pragma unroll
            for (int q = 0; q < 4; q++) acc[i][j][q] = 0.0f;

    const int KT = K >> 5;

    auto load_tile = [&](int st, int k0) {
#pragma unroll
        for (int p = 0; p < 2; p++) {
            int f = tid + p * 256;               // 0..511
            int row = f >> 2, ch = f & 3;        // 128 rows x 4 chunks(8 halves)
            int gm = by * 128 + row;
            cpAsync16(&Ah[st][row * HPITCH + ch * 8],
                      A + (long long)gm * K + k0 + ch * 8,
                      (gm < M) ? 16 : 0);
        }
#pragma unroll
        for (int p = 0; p < 2; p++) {
            int f = tid + p * 256;
            int row = f >> 2, ch = f & 3;
            cpAsync16(&Bh[st][row * HPITCH + ch * 8],
                      Bt + (long long)(bx * 128 + row) * K + k0 + ch * 8,
                      16);
        }
    };

    load_tile(0, 0);
    asm volatile("cp.async.commit_group;");

    for (int kt = 0; kt < KT; kt++) {
        const int st = kt & 1;
        if (kt + 1 < KT) load_tile(st ^ 1, (kt + 1) * 32);
        asm volatile("cp.async.commit_group;");
        asm volatile("cp.async.wait_group 1;");
        __syncthreads();

        const unsigned aSt = aAh0 + (unsigned)(st * 128 * HPITCH * 2) + laneBaseA;
        const unsigned bSt = aBh0 + (unsigned)(st * 128 * HPITCH * 2) + laneBaseB;
#pragma unroll
        for (int ks = 0; ks < 2; ks++) {
            unsigned bf[4][2];
#pragma unroll
            for (int jj = 0; jj < 2; jj++) {
                unsigned addr = bSt + (unsigned)(ks * 32 + jj * 16 * WPITCH * 4);
                asm volatile(
                    "ldmatrix.sync.aligned.m8n8.x4.shared.b16 {%0,%1,%2,%3}, [%4];"
                    : "=r"(bf[jj*2][0]), "=r"(bf[jj*2][1]),
                      "=r"(bf[jj*2+1][0]), "=r"(bf[jj*2+1][1])
                    : "r"(addr));
            }
#pragma unroll
            for (int i = 0; i < 4; i++) {
                unsigned addr = aSt + (unsigned)(i * 16 * HPITCH * 2 + ks * 32);
                unsigned a0, a1, a2, a3;
                asm volatile(
                    "ldmatrix.sync.aligned.m8n8.x4.shared.b16 {%0,%1,%2,%3}, [%4];"
                    : "=r"(a0), "=r"(a1), "=r"(a2), "=r"(a3) : "r"(addr));
#pragma unroll
                for (int j = 0; j < 4; j++) {
                    asm volatile(
                        "mma.sync.aligned.m16n8k16.row.col.f32.f16.f16.f32 "
                        "{%0,%1,%2,%3},{%4,%5,%6,%7},{%8,%9},{%0,%1,%2,%3};\n"
                        : "+f"(acc[i][j][0]), "+f"(acc[i][j][1]),
                          "+f"(acc[i][j][2]), "+f"(acc[i][j][3])
                        : "r"(a0), "r"(a1), "r"(a2), "r"(a3),
                          "r"(bf[j][0]), "r"(bf[j][1]));
                }
            }
        }
        __syncthreads();
    }

    // ---- store C tile as fp16 ----
#pragma unroll
    for (int i = 0; i < 4; i++) {
        int row0 = by * 128 + m0 + i * 16 + r;
#pragma unroll
        for (int j = 0; j < 4; j++) {
            int col = bx * 128 + n0 + j * 8 + 2 * c;
            if (row0 < M)
                *(__half2*)(C + (long long)row0 * DMF + col) =
                    __floats2half2_rn(acc[i][j][0], acc[i][j][1]);
            if (row0 + 8 < M)
                *(__half2*)(C + (long long)(row0 + 8) * DMF + col) =
                    __floats2half2_rn(acc[i][j][2], acc[i][j][3]);
        }
    }

    // ---- fused attention-score epilogue (head == bx); smem reduce ----
    float asr[4][2], adr[4][2];
#pragma unroll
    for (int j = 0; j < 4; j++) {
#pragma unroll
        for (int p = 0; p < 2; p++) {
            int colL = n0 + j * 8 + 2 * c + p;
            asr[j][p] = a_s[bx * HIDD + colL];
            adr[j][p] = a_d[bx * HIDD + colL];
        }
    }
#pragma unroll
    for (int i = 0; i < 4; i++) {
        float ps_lo = 0.f, ps_hi = 0.f, pd_lo = 0.f, pd_hi = 0.f;
#pragma unroll
        for (int j = 0; j < 4; j++) {
            ps_lo = fmaf(acc[i][j][0], asr[j][0], fmaf(acc[i][j][1], asr[j][1], ps_lo));
            ps_hi = fmaf(acc[i][j][2], asr[j][0], fmaf(acc[i][j][3], asr[j][1], ps_hi));
            pd_lo = fmaf(acc[i][j][0], adr[j][0], fmaf(acc[i][j][1], adr[j][1], pd_lo));
            pd_hi = fmaf(acc[i][j][2], adr[j][0], fmaf(acc[i][j][3], adr[j][1], pd_hi));
        }
#pragma unroll
        for (int off = 1; off < 4; off <<= 1) {
            ps_lo += __shfl_xor_sync(0xffffffffu, ps_lo, off);
            ps_hi += __shfl_xor_sync(0xffffffffu, ps_hi, off);
            pd_lo += __shfl_xor_sync(0xffffffffu, pd_lo, off);
            pd_hi += __shfl_xor_sync(0xffffffffu, pd_hi, off);
        }
        if (c == 0) {
            int rl = m0 + i * 16 + r;
            s_ps[wc][rl]     = ps_lo;  s_pd[wc][rl]     = pd_lo;
            s_ps[wc][rl + 8] = ps_hi;  s_pd[wc][rl + 8] = pd_hi;
        }
    }
    __syncthreads();
    if (tid < 128) {
        int row = by * 128 + tid;
        if (row < M) {
            d_ssrc[row * NHEAD + bx] =
                s_ps[0][tid] + s_ps[1][tid] + s_ps[2][tid] + s_ps[3][tid];
            d_sdst[row * NHEAD + bx] =
                s_pd[0][tid] + s_pd[1][tid] + s_pd[2][tid] + s_pd[3][tid];
        }
    }
}

// ---------------- CSR build (once per launch) ----------------
__global__ void count_deg_kernel(const int* __restrict__ ei) {
    int e = blockIdx.x * blockDim.x + threadIdx.x;
    if (e >= ET) return;
    int dst = (e < EE) ? ei[EE + e] : e - EE;
    atomicAdd(&d_deg[dst], 1);
}

__global__ void __launch_bounds__(1024)
scan_kernel() {
    __shared__ int partial[1024];
    const int C = (NN + 1023) / 1024;       // 49
    int t = threadIdx.x;
    int lo = t * C, hi = min(lo + C, NN);
    int s = 0;
    for (int i = lo; i < hi; i++) s += d_deg[i];
    partial[t] = s;
    __syncthreads();
    for (int off = 1; off < 1024; off <<= 1) {
        int v = partial[t];
        int add = (t >= off) ? partial[t - off] : 0;
        __syncthreads();
        partial[t] = v + add;
        __syncthreads();
    }
    int run = (t == 0) ? 0 : partial[t - 1];
    for (int i = lo; i < hi; i++) {
        d_rowptr[i] = run;
        d_cursor[i] = run;
        run += d_deg[i];
    }
}

__global__ void scatter_kernel(const int* __restrict__ ei) {
    int e = blockIdx.x * blockDim.x + threadIdx.x;
    if (e >= ET) return;
    int dst = (e < EE) ? ei[EE + e] : e - EE;
    int pos = atomicAdd(&d_cursor[dst], 1);
    d_eid[pos] = e;
}

// ---------------- warp-per-node fused softmax + fp16 gather ---------------
__global__ void __launch_bounds__(256)
aggregate_warp_kernel(const int* __restrict__ ei,
                      const float* __restrict__ bias) {
    const int lane = threadIdx.x & 31;
    const int n = blockIdx.x * 8 + (threadIdx.x >> 5);
    if (n >= NN) return;

    const int start = d_rowptr[n];
    const int deg   = d_deg[n];
    const int head  = lane >> 3;          // lane's 16 cols = [lane*16, +16)

    float4 sd = *(const float4*)(d_sdst + n * NHEAD);

    // ---- phase 1: per-head segment max (warp-parallel over edges) ----
    float4 m4 = make_float4(-1e30f, -1e30f, -1e30f, -1e30f);
    for (int b = lane; b < deg; b += 32) {
        int e = d_eid[start + b];
        int s = (e < EE) ? ei[e] : e - EE;
        float4 ss = *(const float4*)(d_ssrc + s * NHEAD);
        m4.x = fmaxf(m4.x, leakyf(ss.x + sd.x));
        m4.y = fmaxf(m4.y, leakyf(ss.y + sd.y));
        m4.z = fmaxf(m4.z, leakyf(ss.z + sd.z));
        m4.w = fmaxf(m4.w, leakyf(ss.w + sd.w));
    }
#pragma unroll
    for (int off = 16; off; off >>= 1) {
        m4.x = fmaxf(m4.x, __shfl_xor_sync(0xffffffffu, m4.x, off));
        m4.y = fmaxf(m4.y, __shfl_xor_sync(0xffffffffu, m4.y, off));
        m4.z = fmaxf(m4.z, __shfl_xor_sync(0xffffffffu, m4.z, off));
        m4.w = fmaxf(m4.w, __shfl_xor_sync(0xffffffffu, m4.w, off));
    }

    // ---- phase 2: exp weights + denominator + fp16 weighted gather ----
    float4 acc0 = make_float4(0.f, 0.f, 0.f, 0.f);
    float4 acc1 = acc0, acc2 = acc0, acc3 = acc0;
    float4 lden = acc0;

    for (int base = 0; base < deg; base += 32) {
        int cnt = min(32, deg - base);
        int s = 0;
        float4 w4 = make_float4(0.f, 0.f, 0.f, 0.f);
        if (lane < cnt) {
            int e = d_eid[start + base + lane];
            s = (e < EE) ? ei[e] : e - EE;
            float4 ss = *(const float4*)(d_ssrc + s * NHEAD);
            w4.x = expf(leakyf(ss.x + sd.x) - m4.x);
            w4.y = expf(leakyf(ss.y + sd.y) - m4.y);
            w4.z = expf(leakyf(ss.z + sd.z) - m4.z);
            w4.w = expf(leakyf(ss.w + sd.w) - m4.w);
            lden.x += w4.x; lden.y += w4.y; lden.z += w4.z; lden.w += w4.w;
        }
        for (int i = 0; i < cnt; i++) {
            int   si = __shfl_sync(0xffffffffu, s, i);
            float wx = __shfl_sync(0xffffffffu, w4.x, i);
            float wy = __shfl_sync(0xffffffffu, w4.y, i);
            float wz = __shfl_sync(0xffffffffu, w4.z, i);
            float ww = __shfl_sync(0xffffffffu, w4.w, i);
            float wgt = (head == 0) ? wx : (head == 1) ? wy : (head == 2) ? wz : ww;
            const uint4* hp = (const uint4*)(d_h + (long long)si * DMF) + lane * 2;
            uint4 u0 = hp[0], u1 = hp[1];
            const __half2* p0 = (const __half2*)&u0;
            const __half2* p1 = (const __half2*)&u1;
            float2 f;
            f = __half22float2(p0[0]);
            acc0.x = fmaf(wgt, f.x, acc0.x); acc0.y = fmaf(wgt, f.y, acc0.y);
            f = __half22float2(p0[1]);
            acc0.z = fmaf(wgt, f.x, acc0.z); acc0.w = fmaf(wgt, f.y, acc0.w);
            f = __half22float2(p0[2]);
            acc1.x = fmaf(wgt, f.x, acc1.x); acc1.y = fmaf(wgt, f.y, acc1.y);
            f = __half22float2(p0[3]);
            acc1.z = fmaf(wgt, f.x, acc1.z); acc1.w = fmaf(wgt, f.y, acc1.w);
            f = __half22float2(p1[0]);
            acc2.x = fmaf(wgt, f.x, acc2.x); acc2.y = fmaf(wgt, f.y, acc2.y);
            f = __half22float2(p1[1]);
            acc2.z = fmaf(wgt, f.x, acc2.z); acc2.w = fmaf(wgt, f.y, acc2.w);
            f = __half22float2(p1[2]);
            acc3.x = fmaf(wgt, f.x, acc3.x); acc3.y = fmaf(wgt, f.y, acc3.y);
            f = __half22float2(p1[3]);
            acc3.z = fmaf(wgt, f.x, acc3.z); acc3.w = fmaf(wgt, f.y, acc3.w);
        }
    }

#pragma unroll
    for (int off = 16; off; off >>= 1) {
        lden.x += __shfl_xor_sync(0xffffffffu, lden.x, off);
        lden.y += __shfl_xor_sync(0xffffffffu, lden.y, off);
        lden.z += __shfl_xor_sync(0xffffffffu, lden.z, off);
        lden.w += __shfl_xor_sync(0xffffffffu, lden.w, off);
    }
    float den = (head == 0) ? lden.x : (head == 1) ? lden.y
              : (head == 2) ? lden.z : lden.w;
    float rd = 1.0f / den;

    const float4* bp = (const float4*)bias + lane * 4;
    float4* op = (float4*)(d_agg + (long long)n * DMF) + lane * 4;
    float4 b0 = bp[0], b1 = bp[1], b2 = bp[2], b3 = bp[3];
    float4 o;
    o.x = fmaf(acc0.x, rd, b0.x); o.y = fmaf(acc0.y, rd, b0.y);
    o.z = fmaf(acc0.z, rd, b0.z); o.w = fmaf(acc0.w, rd, b0.w); op[0] = o;
    o.x = fmaf(acc1.x, rd, b1.x); o.y = fmaf(acc1.y, rd, b1.y);
    o.z = fmaf(acc1.z, rd, b1.z); o.w = fmaf(acc1.w, rd, b1.w); op[1] = o;
    o.x = fmaf(acc2.x, rd, b2.x); o.y = fmaf(acc2.y, rd, b2.y);
    o.z = fmaf(acc2.z, rd, b2.z); o.w = fmaf(acc2.w, rd, b2.w); op[2] = o;
    o.x = fmaf(acc3.x, rd, b3.x); o.y = fmaf(acc3.y, rd, b3.y);
    o.z = fmaf(acc3.z, rd, b3.z); o.w = fmaf(acc3.w, rd, b3.w); op[3] = o;
}

// ---------------- batch norm ----------------
__global__ void __launch_bounds__(512)
bn_stats_kernel() {
    int c = threadIdx.x;
    int r0 = blockIdx.x * 64;
    int rend = min(r0 + 64, NN);
    float s = 0.f, ss = 0.f;
    for (int r = r0; r < rend; r++) {
        float v = d_agg[(long long)r * DMF + c];
        s += v; ss += v * v;
    }
    atomicAdd(&d_bnsum[c], s);
    atomicAdd(&d_bnss[c], ss);
}

// finalize consumes the sums and re-zeros them for the next layer
__global__ void bn_finalize_kernel(const float* __restrict__ g,
                                   const float* __restrict__ be) {
    int c = threadIdx.x;
    float mean = d_bnsum[c] * (1.0f / NN);
    float var  = d_bnss[c] * (1.0f / NN) - mean * mean;
    float sc = g[c] * rsqrtf(var + BN_EPS);
    d_scale[c] = sc;
    d_shift[c] = be[c] - mean * sc;
    d_bnsum[c] = 0.f;
    d_bnss[c]  = 0.f;
}

// BN + ReLU -> next-layer A in fp16
__global__ void bn_apply_kernel() {
    int i = blockIdx.x * blockDim.x + threadIdx.x;
    if (i >= NN * DMF / 2) return;
    int c = (2 * i) & (DMF - 1);
    float2 a = *(const float2*)(d_agg + 2 * i);
    float vx = fmaxf(fmaf(a.x, d_scale[c],     d_shift[c]),     0.f);
    float vy = fmaxf(fmaf(a.y, d_scale[c + 1], d_shift[c + 1]), 0.f);
    *((__half2*)d_xbh + i) = __floats2half2_rn(vx, vy);
}

// last layer: BN + ReLU + mean/max pooling fused
__global__ void bn_apply_pool_kernel(const int* __restrict__ batch) {
    int i = blockIdx.x * blockDim.x + threadIdx.x;
    if (i >= NN * 128) return;              // float4 lanes
    int n = i >> 7, c4 = i & 127;
    int c = c4 * 4;
    float4 a = *(const float4*)(d_agg + (long long)n * DMF + c);
    float4 v;
    v.x = fmaxf(fmaf(a.x, d_scale[c + 0], d_shift[c + 0]), 0.f);
    v.y = fmaxf(fmaf(a.y, d_scale[c + 1], d_shift[c + 1]), 0.f);
    v.z = fmaxf(fmaf(a.z, d_scale[c + 2], d_shift[c + 2]), 0.f);
    v.w = fmaxf(fmaf(a.w, d_scale[c + 3], d_shift[c + 3]), 0.f);
    int g = batch[n];
    redAddV4(d_gsum + (long long)g * DMF + c, v);
    int* mp = d_gmaxi + (long long)g * DMF + c;
    atomicMax(mp + 0, __float_as_int(v.x));   // values >= 0 after ReLU
    atomicMax(mp + 1, __float_as_int(v.y));
    atomicMax(mp + 2, __float_as_int(v.z));
    atomicMax(mp + 3, __float_as_int(v.w));
}

// ---------------- pooling init ----------------
__global__ void pool_init_kernel() {
    int i = blockIdx.x * blockDim.x + threadIdx.x;
    if (i < GG * DMF) { d_gsum[i] = 0.f; d_gmaxi[i] = 0; }
    if (i < GG) d_gcnt[i] = 0.f;
}

__global__ void pool_cnt_kernel(const int* __restrict__ batch) {
    int n = blockIdx.x * blockDim.x + threadIdx.x;
    if (n < NN) atomicAdd(&d_gcnt[batch[n]], 1.0f);
}

// ---------------- graph-level MLP ----------------
__global__ void __launch_bounds__(128)
mlp1_kernel(const float* __restrict__ c1w, const float* __restrict__ c1b) {
    __shared__ float hrow[8][1024];
    int g0 = blockIdx.x * 8, t = threadIdx.x;
#pragma unroll
    for (int gi = 0; gi < 8; gi++) {
        int g = g0 + gi;
        float inv = 1.0f / fmaxf(d_gcnt[g], 1.0f);
        for (int c = t; c < DMF; c += 128) {
            hrow[gi][c]       = d_gsum[g * DMF + c] * inv;
            hrow[gi][DMF + c] = __int_as_float(d_gmaxi[g * DMF + c]);
        }
    }
    __syncthreads();
    float acc[8];
    float b = c1b[t];
#pragma unroll
    for (int gi = 0; gi < 8; gi++) acc[gi] = b;
    for (int k = 0; k < 1024; k++) {
        float wv = c1w[k * 128 + t];
#pragma unroll
        for (int gi = 0; gi < 8; gi++)
            acc[gi] = fmaf(hrow[gi][k], wv, acc[gi]);
    }
#pragma unroll
    for (int gi = 0; gi < 8; gi++)
        d_h1[(g0 + gi) * 128 + t] = fmaxf(acc[gi], 0.f);
}

__global__ void __launch_bounds__(64)
mlp2_kernel(const float* __restrict__ c2w, const float* __restrict__ c2b) {
    __shared__ float hrow[128];
    int g = blockIdx.x, t = threadIdx.x;
    for (int c = t; c < 128; c += 64) hrow[c] = d_h1[g * 128 + c];
    __syncthreads();
    float acc = c2b[t];
    for (int k = 0; k < 128; k++) acc = fmaf(hrow[k], c2w[k * 64 + t], acc);
    d_h2[g * 64 + t] = fmaxf(acc, 0.f);
}

__global__ void mlp3_kernel(const float* __restrict__ c3w,
                            const float* __restrict__ c3b,
                            float* __restrict__ out) {
    int g = blockIdx.x * blockDim.x + threadIdx.x;
    if (g >= GG) return;
    float acc = c3b[0];
    for (int k = 0; k < 64; k++) acc = fmaf(d_h2[g * 64 + k], c3w[k], acc);
    out[g] = 1.0f / (1.0f + expf(-acc));
}

// ---------------- launch ----------------
extern "C" void kernel_launch(void* const* d_in, const int* in_sizes, int n_in,
                              void* d_out, int out_size) {
    const float* x     = (const float*)d_in[0];
    const int*   ei    = (const int*)  d_in[1];
    const int*   batch = (const int*)  d_in[2];

    const float* W [3] = {(const float*)d_in[3],  (const float*)d_in[9],  (const float*)d_in[15]};
    const float* AS[3] = {(const float*)d_in[4],  (const float*)d_in[10], (const float*)d_in[16]};
    const float* AD[3] = {(const float*)d_in[5],  (const float*)d_in[11], (const float*)d_in[17]};
    const float* BB[3] = {(const float*)d_in[6],  (const float*)d_in[12], (const float*)d_in[18]};
    const float* GM[3] = {(const float*)d_in[7],  (const float*)d_in[13], (const float*)d_in[19]};
    const float* BE[3] = {(const float*)d_in[8],  (const float*)d_in[14], (const float*)d_in[20]};

    const float* c1w = (const float*)d_in[21];
    const float* c1b = (const float*)d_in[22];
    const float* c2w = (const float*)d_in[23];
    const float* c2b = (const float*)d_in[24];
    const float* c3w = (const float*)d_in[25];
    const float* c3b = (const float*)d_in[26];
    float* out = (float*)d_out;

    __half* hbuf;  cudaGetSymbolAddress((void**)&hbuf,  d_h);
    __half* xhb;   cudaGetSymbolAddress((void**)&xhb,   d_xh);
    __half* xbhb;  cudaGetSymbolAddress((void**)&xbhb,  d_xbh);
    __half* wt0;   cudaGetSymbolAddress((void**)&wt0,   d_wt0);
    __half* wt1;   cudaGetSymbolAddress((void**)&wt1,   d_wt1);
    __half* wt2;   cudaGetSymbolAddress((void**)&wt2,   d_wt2);
    __half* WT[3] = {wt0, wt1, wt2};

    const int KDIM[3] = {64, DMF, DMF};
    const int THR = 256;

    // ---- init + conversions + all weight transposes up-front ----
    init_zero_kernel<<<(NN + THR - 1) / THR, THR>>>();

    int cxt = NN * 64 / 2;
    convert_x_kernel<<<(cxt + THR - 1) / THR, THR>>>(x);

    for (int l = 0; l < 3; l++) {
        dim3 tg(DMF / 32, KDIM[l] / 32);
        transpose_w_kernel<<<tg, 256>>>(W[l], WT[l], KDIM[l]);
    }

    dim3 ggrid(DMF / 128, (NN + 127) / 128);
    gemm_f16_kernel<<<ggrid, 256>>>(xhb, wt0, hbuf, NN, KDIM[0], AS[0], AD[0]);

    // ---- CSR build + pooling init (independent of GEMM) ----
    count_deg_kernel<<<(ET + THR - 1) / THR, THR>>>(ei);
    scan_kernel<<<1, 1024>>>();
    scatter_kernel<<<(ET + THR - 1) / THR, THR>>>(ei);

    int pil = GG * DMF;
    pool_init_kernel<<<(pil + THR - 1) / THR, THR>>>();
    pool_cnt_kernel<<<(NN + THR - 1) / THR, THR>>>(batch);

    for (int l = 0; l < 3; l++) {
        if (l > 0)
            gemm_f16_kernel<<<ggrid, 256>>>(xbhb, WT[l], hbuf, NN, KDIM[l], AS[l], AD[l]);

        aggregate_warp_kernel<<<(NN + 7) / 8, 256>>>(ei, BB[l]);

        bn_stats_kernel<<<(NN + 63) / 64, DMF>>>();
        bn_finalize_kernel<<<1, DMF>>>(GM[l], BE[l]);

        if (l < 2) {
            int nel = NN * DMF / 2;
            bn_apply_kernel<<<(nel + THR - 1) / THR, THR>>>();
        } else {
            int pft = NN * 128;
            bn_apply_pool_kernel<<<(pft + THR - 1) / THR, THR>>>(batch);
        }
    }

    mlp1_kernel<<<GG / 8, 128>>>(c1w, c1b);
    mlp2_kernel<<<GG, 64>>>(c2w, c2b);
    mlp3_kernel<<<(GG + 63) / 64, 64>>>(c3w, c3b, out);
}